// round 13
// baseline (speedup 1.0000x reference)
#include <cuda_runtime.h>
#include <cuda_fp16.h>
#include <math.h>
#include <stdint.h>

#define NN 100000
#define NE 1600000

// ---------------- scratch (device globals) ----------------
__device__ __half g_yh[(size_t)NN * 128];   // Y ping
__device__ __half g_h[(size_t)NN * 128];    // Y pong
__device__ float  g_dinv[NN];
__device__ int    g_cnt[NN];
__device__ int    g_excl[NN];
__device__ int    g_bsum[128];
__device__ int    g_rowptr[NN + 1];
__device__ int    g_cursor[NN];
__device__ int    g_col[NE];

// ---------------- prep ----------------
__global__ void zero_cnt(int* cnt, int n) {
    int i = blockIdx.x * blockDim.x + threadIdx.x;
    if (i < n) cnt[i] = 0;
}

__global__ void count_deg(const int* __restrict__ dst, int* __restrict__ cnt, int E, int N) {
    int e = blockIdx.x * blockDim.x + threadIdx.x;
    if (e >= E) return;
    int d = dst[e];
    if ((unsigned)d < (unsigned)N) atomicAdd(&cnt[d], 1);
}

__global__ void scan_block_dinv(const int* __restrict__ cnt, int* __restrict__ excl,
                                int* __restrict__ bsum, float* __restrict__ dinv, int n) {
    __shared__ int sh[1024];
    int tid = threadIdx.x;
    int i = blockIdx.x * 1024 + tid;
    int v = (i < n) ? cnt[i] : 0;
    if (i < n) dinv[i] = rsqrtf((float)(v + 1));
    sh[tid] = v;
    __syncthreads();
#pragma unroll
    for (int off = 1; off < 1024; off <<= 1) {
        int t = (tid >= off) ? sh[tid - off] : 0;
        __syncthreads();
        sh[tid] += t;
        __syncthreads();
    }
    if (i < n) excl[i] = sh[tid] - v;
    if (tid == 1023) bsum[blockIdx.x] = sh[1023];
}

__global__ void scan_partials(int* bsum, int nb) {
    __shared__ int sh[128];
    int tid = threadIdx.x;
    int v = (tid < nb) ? bsum[tid] : 0;
    sh[tid] = v;
    __syncthreads();
#pragma unroll
    for (int off = 1; off < 128; off <<= 1) {
        int t = (tid >= off) ? sh[tid - off] : 0;
        __syncthreads();
        sh[tid] += t;
        __syncthreads();
    }
    if (tid < nb) bsum[tid] = sh[tid] - v;
}

__global__ void scan_finish(const int* __restrict__ excl, const int* __restrict__ bsum,
                            int* __restrict__ rowptr, int* __restrict__ cursor, int n, int E) {
    int i = blockIdx.x * blockDim.x + threadIdx.x;
    if (i < n) {
        int v = excl[i] + bsum[i >> 10];
        rowptr[i] = v;
        cursor[i] = v;
    } else if (i == n) {
        rowptr[n] = E;
    }
}

__global__ void fill_csr(const int* __restrict__ src, const int* __restrict__ dst,
                         int* __restrict__ cursor, int* __restrict__ col, int E, int N) {
    int e = blockIdx.x * blockDim.x + threadIdx.x;
    if (e >= E) return;
    int d = dst[e];
    if ((unsigned)d >= (unsigned)N) return;
    int p = atomicAdd(&cursor[d], 1);
    col[p] = src[e];
}

// ---------------- MMA / LDSM macros ----------------
#define LDSM_X4(r0, r1, r2, r3, addr) \
    asm volatile("ldmatrix.sync.aligned.m8n8.x4.shared.b16 {%0,%1,%2,%3}, [%4];" \
                 : "=r"(r0), "=r"(r1), "=r"(r2), "=r"(r3) : "r"(addr))
#define LDSM_X4_T(r0, r1, r2, r3, addr) \
    asm volatile("ldmatrix.sync.aligned.m8n8.x4.trans.shared.b16 {%0,%1,%2,%3}, [%4];" \
                 : "=r"(r0), "=r"(r1), "=r"(r2), "=r"(r3) : "r"(addr))
#define MMA_16816(d, a, b) \
    asm volatile("mma.sync.aligned.m16n8k16.row.col.f32.f16.f16.f32 " \
                 "{%0,%1,%2,%3}, {%4,%5,%6,%7}, {%8,%9}, {%0,%1,%2,%3};" \
                 : "+f"(d[0]), "+f"(d[1]), "+f"(d[2]), "+f"(d[3]) \
                 : "r"(a[0]), "r"(a[1]), "r"(a[2]), "r"(a[3]), "r"(b[0]), "r"(b[1]))

template <int FO>
__device__ __forceinline__ void stage_w(const float* __restrict__ W, char* Ws, int tid) {
    constexpr int WROWB = FO * 2;
    for (int i = tid; i < 128 * FO / 4; i += 256) {
        int k = i / (FO / 4);
        int c4 = i % (FO / 4);
        float4 v = ((const float4*)W)[(size_t)k * (FO / 4) + c4];
        __half2 h0 = __floats2half2_rn(v.x, v.y);
        __half2 h1 = __floats2half2_rn(v.z, v.w);
        uint2 u;
        u.x = *(unsigned*)&h0;
        u.y = *(unsigned*)&h1;
        int chunk = c4 >> 1;
        *(uint2*)&Ws[k * WROWB + (((chunk ^ (k & 7)) << 4) | ((c4 & 1) << 3))] = u;
    }
}

// shared HMMA mainloop + epilogue (Y output scaled by dinv when SCALE)
template <int FO, bool SCALE>
__device__ __forceinline__ void tile_compute(unsigned xs_base, unsigned ws_base,
                                             const float* __restrict__ dinv,
                                             __half* __restrict__ Yh, int row0, int N,
                                             int warp_m, int warp_n, int l) {
    constexpr int WN = FO / 2;
    constexpr int NFRAG = WN / 8;
    constexpr int XROWB = 256;
    constexpr int WROWB = FO * 2;

    float acc[2][NFRAG][4];
#pragma unroll
    for (int mf = 0; mf < 2; mf++)
#pragma unroll
        for (int nf = 0; nf < NFRAG; nf++)
#pragma unroll
            for (int c = 0; c < 4; c++) acc[mf][nf][c] = 0.f;

#pragma unroll
    for (int ks = 0; ks < 8; ks++) {
        unsigned a[2][4];
#pragma unroll
        for (int mf = 0; mf < 2; mf++) {
            int row = warp_m * 32 + mf * 16 + (l & 15);
            int colh = ks * 16 + (l >> 4) * 8;
            unsigned addr = xs_base + row * XROWB + ((((colh >> 3) ^ (row & 7))) << 4);
            LDSM_X4(a[mf][0], a[mf][1], a[mf][2], a[mf][3], addr);
        }
        unsigned b[NFRAG][2];
#pragma unroll
        for (int g2 = 0; g2 < NFRAG / 2; g2++) {
            int brow = ks * 16 + (l & 15);
            int bcol = warp_n * WN + g2 * 16 + (l >> 4) * 8;
            unsigned addr = ws_base + brow * WROWB + ((((bcol >> 3) ^ (brow & 7))) << 4);
            unsigned r0, r1, r2, r3;
            LDSM_X4_T(r0, r1, r2, r3, addr);
            b[2 * g2][0] = r0; b[2 * g2][1] = r1;
            b[2 * g2 + 1][0] = r2; b[2 * g2 + 1][1] = r3;
        }
#pragma unroll
        for (int mf = 0; mf < 2; mf++)
#pragma unroll
            for (int nf = 0; nf < NFRAG; nf++)
                MMA_16816(acc[mf][nf], a[mf], b[nf]);
    }

    int g = l >> 2;
    int c2 = (l & 3) * 2;
#pragma unroll
    for (int mf = 0; mf < 2; mf++) {
        int r_lo = row0 + warp_m * 32 + mf * 16 + g;
        int r_hi = r_lo + 8;
        float di_lo = 1.f, di_hi = 1.f;
        if (SCALE) {
            di_lo = (r_lo < N) ? dinv[r_lo] : 0.f;
            di_hi = (r_hi < N) ? dinv[r_hi] : 0.f;
        }
#pragma unroll
        for (int nf = 0; nf < NFRAG; nf++) {
            int col = warp_n * WN + nf * 8 + c2;
            if (r_lo < N) {
                __half2 h = SCALE ? __floats2half2_rn(di_lo * acc[mf][nf][0], di_lo * acc[mf][nf][1])
                                  : __floats2half2_rn(acc[mf][nf][0], acc[mf][nf][1]);
                *(__half2*)&Yh[(size_t)r_lo * FO + col] = h;
            }
            if (r_hi < N) {
                __half2 h = SCALE ? __floats2half2_rn(di_hi * acc[mf][nf][2], di_hi * acc[mf][nf][3])
                                  : __floats2half2_rn(acc[mf][nf][2], acc[mf][nf][3]);
                *(__half2*)&Yh[(size_t)r_hi * FO + col] = h;
            }
        }
    }
}

// ---------------- gemm1: fp32 input, UNSCALED output (no prep dependency) ----------------
__launch_bounds__(256, 2)
__global__ void gemm_hmma_f32(const float* __restrict__ Xin, const float* __restrict__ W,
                              __half* __restrict__ Yh, int N) {
    constexpr int FO = 128;
    constexpr int BM = 128;
    constexpr int XROWB = 256;

    extern __shared__ char sm[];
    char* Xs = sm;
    char* Ws = sm + BM * XROWB;

    int tid = threadIdx.x;
    int warp = tid >> 5;
    int l = tid & 31;
    int warp_m = warp & 3;
    int warp_n = warp >> 2;

    stage_w<FO>(W, Ws, tid);

    unsigned xs_base = (unsigned)__cvta_generic_to_shared(Xs);
    unsigned ws_base = (unsigned)__cvta_generic_to_shared(Ws);

    int tiles = (N + BM - 1) / BM;
    int t = blockIdx.x;
    uint4 pf[8];

    auto ldg_tile = [&](int row0) {
#pragma unroll
        for (int j = 0; j < 8; j++) {
            int i = tid + j * 256;
            int r = i >> 4;
            int q = i & 15;
            int gr = row0 + r;
            uint4 v = make_uint4(0, 0, 0, 0);
            if (gr < N) {
                const float4* p = (const float4*)Xin + (size_t)gr * 32 + q * 2;
                float4 f0 = p[0];
                float4 f1 = p[1];
                __half2 h0 = __floats2half2_rn(f0.x, f0.y);
                __half2 h1 = __floats2half2_rn(f0.z, f0.w);
                __half2 h2 = __floats2half2_rn(f1.x, f1.y);
                __half2 h3 = __floats2half2_rn(f1.z, f1.w);
                v.x = *(unsigned*)&h0;
                v.y = *(unsigned*)&h1;
                v.z = *(unsigned*)&h2;
                v.w = *(unsigned*)&h3;
            }
            pf[j] = v;
        }
    };

    if (t < tiles) ldg_tile(t * BM);

    for (; t < tiles; t += gridDim.x) {
        int row0 = t * BM;
#pragma unroll
        for (int j = 0; j < 8; j++) {
            int i = tid + j * 256;
            int r = i >> 4;
            int q = i & 15;
            *(uint4*)&Xs[r * XROWB + ((q ^ (r & 7)) << 4)] = pf[j];
        }
        __syncthreads();
        int tn = t + gridDim.x;
        if (tn < tiles) ldg_tile(tn * BM);
        tile_compute<FO, false>(xs_base, ws_base, nullptr, Yh, row0, N, warp_m, warp_n, l);
        __syncthreads();
    }
}

// ---------------- helpers ----------------
__device__ __forceinline__ void unpack_add8(uint4 u, float* acc) {
    float2 f;
    f = __half22float2(*(__half2*)&u.x); acc[0] += f.x; acc[1] += f.y;
    f = __half22float2(*(__half2*)&u.y); acc[2] += f.x; acc[3] += f.y;
    f = __half22float2(*(__half2*)&u.z); acc[4] += f.x; acc[5] += f.y;
    f = __half22float2(*(__half2*)&u.w); acc[6] += f.x; acc[7] += f.y;
}
__device__ __forceinline__ void unpack_fma8(uint4 u, float s, float* acc) {
    float2 f;
    f = __half22float2(*(__half2*)&u.x); acc[0] = fmaf(s, f.x, acc[0]); acc[1] = fmaf(s, f.y, acc[1]);
    f = __half22float2(*(__half2*)&u.y); acc[2] = fmaf(s, f.x, acc[2]); acc[3] = fmaf(s, f.y, acc[3]);
    f = __half22float2(*(__half2*)&u.z); acc[4] = fmaf(s, f.x, acc[4]); acc[5] = fmaf(s, f.y, acc[5]);
    f = __half22float2(*(__half2*)&u.w); acc[6] = fmaf(s, f.x, acc[6]); acc[7] = fmaf(s, f.y, acc[7]);
}
__device__ __forceinline__ void unpack_add4(uint2 u, float* acc) {
    float2 f;
    f = __half22float2(*(__half2*)&u.x); acc[0] += f.x; acc[1] += f.y;
    f = __half22float2(*(__half2*)&u.y); acc[2] += f.x; acc[3] += f.y;
}

// ---------------- FUSED: agg(+relu+bias) -> smem tile -> HMMA -> Y out ----------------
// PEREDGE: input Y is unscaled -> multiply each gathered row by dinv[s] (layer-1 agg).
// Input Y always 128 ch; output FO ch, scaled by dinv[r].
template <int FO, bool PEREDGE>
__launch_bounds__(256, 2)
__global__ void fused_agg_gemm(const int* __restrict__ rowptr, const int* __restrict__ col,
                               const __half* __restrict__ Yin, const float* __restrict__ dinv,
                               const float* __restrict__ bias, const float* __restrict__ W,
                               __half* __restrict__ Yout, int N) {
    constexpr int XROWB = 256;
    extern __shared__ char sm[];
    char* Xs = sm;                         // 128 x 256B fp16 swizzled h-tile
    char* Ws = sm + 128 * XROWB;

    int tid = threadIdx.x;
    int warp = tid >> 5;
    int l = tid & 31;
    int hw = tid >> 4;       // half-warp 0..15
    int l16 = tid & 15;
    int row0 = blockIdx.x * 128;

    stage_w<FO>(W, Ws, tid);

    const uint4* Y4 = (const uint4*)Yin;

    // phase 1: each half-warp aggregates 8 nodes -> smem rows
    for (int k = 0; k < 8; k++) {
        int r = hw * 8 + k;              // smem row 0..127
        int node = row0 + r;
        uint4 u = make_uint4(0, 0, 0, 0);
        if (node < N) {
            float di = dinv[node];
            float acc[8];
#pragma unroll
            for (int q = 0; q < 8; q++) acc[q] = 0.f;
            // self-loop
            if (PEREDGE) unpack_fma8(Y4[(size_t)node * 16 + l16], di, acc);
            else         unpack_add8(Y4[(size_t)node * 16 + l16], acc);

            int end = rowptr[node + 1];
            int j = rowptr[node];
            for (; j + 3 < end; j += 4) {
                int s0 = __ldg(&col[j]);
                int s1 = __ldg(&col[j + 1]);
                int s2 = __ldg(&col[j + 2]);
                int s3 = __ldg(&col[j + 3]);
                uint4 a = Y4[(size_t)s0 * 16 + l16];
                uint4 b = Y4[(size_t)s1 * 16 + l16];
                uint4 c = Y4[(size_t)s2 * 16 + l16];
                uint4 d = Y4[(size_t)s3 * 16 + l16];
                if (PEREDGE) {
                    float d0 = __ldg(&dinv[s0]);
                    float d1 = __ldg(&dinv[s1]);
                    float d2 = __ldg(&dinv[s2]);
                    float d3 = __ldg(&dinv[s3]);
                    unpack_fma8(a, d0, acc);
                    unpack_fma8(b, d1, acc);
                    unpack_fma8(c, d2, acc);
                    unpack_fma8(d, d3, acc);
                } else {
                    unpack_add8(a, acc);
                    unpack_add8(b, acc);
                    unpack_add8(c, acc);
                    unpack_add8(d, acc);
                }
            }
            for (; j < end; j++) {
                int s = __ldg(&col[j]);
                uint4 a = Y4[(size_t)s * 16 + l16];
                if (PEREDGE) {
                    float ds = __ldg(&dinv[s]);
                    unpack_fma8(a, ds, acc);
                } else {
                    unpack_add8(a, acc);
                }
            }
            // h = relu(dinv*acc + bias), pack to fp16
            float4 b0 = ((const float4*)bias)[l16 * 2];
            float4 b1 = ((const float4*)bias)[l16 * 2 + 1];
            __half2 p0 = __floats2half2_rn(fmaxf(fmaf(di, acc[0], b0.x), 0.f),
                                           fmaxf(fmaf(di, acc[1], b0.y), 0.f));
            __half2 p1 = __floats2half2_rn(fmaxf(fmaf(di, acc[2], b0.z), 0.f),
                                           fmaxf(fmaf(di, acc[3], b0.w), 0.f));
            __half2 p2 = __floats2half2_rn(fmaxf(fmaf(di, acc[4], b1.x), 0.f),
                                           fmaxf(fmaf(di, acc[5], b1.y), 0.f));
            __half2 p3 = __floats2half2_rn(fmaxf(fmaf(di, acc[6], b1.z), 0.f),
                                           fmaxf(fmaf(di, acc[7], b1.w), 0.f));
            u.x = *(unsigned*)&p0;
            u.y = *(unsigned*)&p1;
            u.z = *(unsigned*)&p2;
            u.w = *(unsigned*)&p3;
        }
        // swizzled smem store: chunk index = l16, row = r
        *(uint4*)&Xs[r * XROWB + ((l16 ^ (r & 7)) << 4)] = u;
    }
    __syncthreads();

    // phase 2: HMMA tile (output scaled by dinv[r])
    unsigned xs_base = (unsigned)__cvta_generic_to_shared(Xs);
    unsigned ws_base = (unsigned)__cvta_generic_to_shared(Ws);
    tile_compute<FO, true>(xs_base, ws_base, dinv, Yout, row0, N,
                           warp & 3, warp >> 2, l);
}

// ---------------- final layer: half-warp gather + log_softmax over 64 ch ----------------
__global__ void agg_lsm64(const int* __restrict__ rowptr, const int* __restrict__ col,
                          const __half* __restrict__ Yh, const float* __restrict__ dinv,
                          const float* __restrict__ bias, float4* __restrict__ Out, int N) {
    int node = (blockIdx.x * blockDim.x + threadIdx.x) >> 5;
    int lane = threadIdx.x & 31;
    if (node >= N) return;
    int hf = lane >> 4;
    int l16 = lane & 15;
    const uint2* Y2 = (const uint2*)Yh;

    float acc[4];
#pragma unroll
    for (int k = 0; k < 4; k++) acc[k] = 0.f;
    if (hf == 0)
        unpack_add4(Y2[(size_t)node * 16 + l16], acc);

    int end = rowptr[node + 1];
    int j = rowptr[node] + hf;
    for (; j + 6 < end; j += 8) {
        int s0 = __ldg(&col[j]);
        int s1 = __ldg(&col[j + 2]);
        int s2 = __ldg(&col[j + 4]);
        int s3 = __ldg(&col[j + 6]);
        uint2 a = Y2[(size_t)s0 * 16 + l16];
        uint2 b = Y2[(size_t)s1 * 16 + l16];
        uint2 c = Y2[(size_t)s2 * 16 + l16];
        uint2 d = Y2[(size_t)s3 * 16 + l16];
        unpack_add4(a, acc);
        unpack_add4(b, acc);
        unpack_add4(c, acc);
        unpack_add4(d, acc);
    }
    for (; j + 2 < end; j += 4) {
        int s0 = __ldg(&col[j]);
        int s1 = __ldg(&col[j + 2]);
        uint2 a = Y2[(size_t)s0 * 16 + l16];
        uint2 b = Y2[(size_t)s1 * 16 + l16];
        unpack_add4(a, acc);
        unpack_add4(b, acc);
    }
    for (; j < end; j += 2) {
        int s = __ldg(&col[j]);
        unpack_add4(Y2[(size_t)s * 16 + l16], acc);
    }
#pragma unroll
    for (int k = 0; k < 4; k++)
        acc[k] += __shfl_xor_sync(0xFFFFFFFFu, acc[k], 16);

    float di = dinv[node];
    float4 b = ((const float4*)bias)[l16];
    float v0 = fmaf(di, acc[0], b.x);
    float v1 = fmaf(di, acc[1], b.y);
    float v2 = fmaf(di, acc[2], b.z);
    float v3 = fmaf(di, acc[3], b.w);
    float m = fmaxf(fmaxf(v0, v1), fmaxf(v2, v3));
#pragma unroll
    for (int o = 8; o > 0; o >>= 1)
        m = fmaxf(m, __shfl_xor_sync(0xFFFFFFFFu, m, o));
    float s = expf(v0 - m) + expf(v1 - m) + expf(v2 - m) + expf(v3 - m);
#pragma unroll
    for (int o = 8; o > 0; o >>= 1)
        s += __shfl_xor_sync(0xFFFFFFFFu, s, o);
    float ls = m + logf(s);
    if (hf == 0)
        Out[(size_t)node * 16 + l16] = make_float4(v0 - ls, v1 - ls, v2 - ls, v3 - ls);
}

// ---------------- driver ----------------
extern "C" void kernel_launch(void* const* d_in, const int* in_sizes, int n_in,
                              void* d_out, int out_size) {
    const float* x   = (const float*)d_in[0];
    const int*   ei  = (const int*)d_in[1];
    const float* W1  = (const float*)d_in[2];
    const float* b1  = (const float*)d_in[3];
    const float* W2  = (const float*)d_in[4];
    const float* b2  = (const float*)d_in[5];
    const float* W3  = (const float*)d_in[6];
    const float* b3  = (const float*)d_in[7];
    float* out = (float*)d_out;

    int N = in_sizes[0] / 128;
    int E = in_sizes[1] / 2;
    const int* src = ei;
    const int* dst = ei + E;

    __half *yh, *y2;
    float* dinv;
    int *cnt, *excl, *bsum, *rowptr, *cursor, *col;
    cudaGetSymbolAddress((void**)&yh, g_yh);
    cudaGetSymbolAddress((void**)&y2, g_h);
    cudaGetSymbolAddress((void**)&dinv, g_dinv);
    cudaGetSymbolAddress((void**)&cnt, g_cnt);
    cudaGetSymbolAddress((void**)&excl, g_excl);
    cudaGetSymbolAddress((void**)&bsum, g_bsum);
    cudaGetSymbolAddress((void**)&rowptr, g_rowptr);
    cudaGetSymbolAddress((void**)&cursor, g_cursor);
    cudaGetSymbolAddress((void**)&col, g_col);

    static cudaStream_t s_side = 0;
    static cudaEvent_t ev_fork = 0, ev_join = 0;
    static bool inited = false;
    if (!inited) {
        inited = true;
        if (cudaStreamCreateWithFlags(&s_side, cudaStreamNonBlocking) != cudaSuccess)
            s_side = 0;
        if (s_side) {
            if (cudaEventCreateWithFlags(&ev_fork, cudaEventDisableTiming) != cudaSuccess ||
                cudaEventCreateWithFlags(&ev_join, cudaEventDisableTiming) != cudaSuccess)
                s_side = 0;
        }
    }
    bool fork = (s_side != 0);
    cudaStream_t sc = fork ? s_side : 0;

    constexpr int SMEM_G1  = 128 * 256 + 128 * 256;  // 64 KB
    constexpr int SMEM_F128 = 128 * 256 + 128 * 256; // 64 KB (Xs 32K + W 32K)
    constexpr int SMEM_F64  = 128 * 256 + 128 * 128; // 48 KB
    cudaFuncSetAttribute(gemm_hmma_f32, cudaFuncAttributeMaxDynamicSharedMemorySize, SMEM_G1);
    cudaFuncSetAttribute(fused_agg_gemm<128, true>,
                         cudaFuncAttributeMaxDynamicSharedMemorySize, SMEM_F128);
    cudaFuncSetAttribute(fused_agg_gemm<64, false>,
                         cudaFuncAttributeMaxDynamicSharedMemorySize, SMEM_F64);

    int nb_nodes = (N + 255) / 256;
    int nb_edges = (E + 255) / 256;
    int nb_scan  = (N + 1023) / 1024;
    int tiles = (N + 127) / 128;
    int gemm_blocks = tiles < 296 ? tiles : 296;
    int lsm_blocks = (int)(((size_t)N * 32 + 255) / 256);

    // ---- fork: prep on side stream || gemm1 on default ----
    if (fork) {
        cudaEventRecord(ev_fork, 0);
        cudaStreamWaitEvent(s_side, ev_fork, 0);
    }
    zero_cnt<<<nb_nodes, 256, 0, sc>>>(cnt, N);
    count_deg<<<nb_edges, 256, 0, sc>>>(dst, cnt, E, N);
    scan_block_dinv<<<nb_scan, 1024, 0, sc>>>(cnt, excl, bsum, dinv, N);
    gemm_hmma_f32<<<gemm_blocks, 256, SMEM_G1>>>(x, W1, yh, N);   // default stream (4th launch)
    scan_partials<<<1, 128, 0, sc>>>(bsum, nb_scan);
    scan_finish<<<(N + 256) / 256, 256, 0, sc>>>(excl, bsum, rowptr, cursor, N, E);
    fill_csr<<<nb_edges, 256, 0, sc>>>(src, dst, cursor, col, E, N);
    if (fork) {
        cudaEventRecord(ev_join, s_side);
        cudaStreamWaitEvent(0, ev_join, 0);
    }

    // ---- fused layer 2: agg(Y1, per-edge dinv) + relu(b1) + @W2 -> Y2 ----
    fused_agg_gemm<128, true><<<tiles, 256, SMEM_F128>>>(rowptr, col, yh, dinv, b1, W2, y2, N);
    // ---- fused layer 3: agg(Y2) + relu(b2) + @W3 -> Y3 (64 ch) ----
    fused_agg_gemm<64, false><<<tiles, 256, SMEM_F64>>>(rowptr, col, y2, dinv, b2, W3, yh, N);
    // ---- final: agg(Y3) + bias b3 + log_softmax ----
    agg_lsm64<<<lsm_blocks, 256>>>(rowptr, col, yh, dinv, b3, (float4*)out, N);
}

// round 14
// speedup vs baseline: 1.2375x; 1.2375x over previous
#include <cuda_runtime.h>
#include <cuda_fp16.h>
#include <math.h>
#include <stdint.h>

#define NN 100000
#define NE 1600000

// ---------------- scratch (device globals) ----------------
__device__ __half g_yh[(size_t)NN * 128];
__device__ __half g_h[(size_t)NN * 128];
__device__ float  g_dinv[NN];
__device__ int    g_cnt[NN];
__device__ int    g_excl[NN];
__device__ int    g_bsum[128];
__device__ int    g_rowptr[NN + 1];
__device__ int    g_cursor[NN];
__device__ int    g_col[NE];

// ---------------- prep ----------------
__global__ void zero_cnt(int* cnt, int n) {
    int i = blockIdx.x * blockDim.x + threadIdx.x;
    if (i < n) cnt[i] = 0;
}

__global__ void count_deg(const int* __restrict__ dst, int* __restrict__ cnt, int E, int N) {
    int e = blockIdx.x * blockDim.x + threadIdx.x;
    if (e >= E) return;
    int d = dst[e];
    if ((unsigned)d < (unsigned)N) atomicAdd(&cnt[d], 1);
}

__global__ void scan_block_dinv(const int* __restrict__ cnt, int* __restrict__ excl,
                                int* __restrict__ bsum, float* __restrict__ dinv, int n) {
    __shared__ int sh[1024];
    int tid = threadIdx.x;
    int i = blockIdx.x * 1024 + tid;
    int v = (i < n) ? cnt[i] : 0;
    if (i < n) dinv[i] = rsqrtf((float)(v + 1));
    sh[tid] = v;
    __syncthreads();
#pragma unroll
    for (int off = 1; off < 1024; off <<= 1) {
        int t = (tid >= off) ? sh[tid - off] : 0;
        __syncthreads();
        sh[tid] += t;
        __syncthreads();
    }
    if (i < n) excl[i] = sh[tid] - v;
    if (tid == 1023) bsum[blockIdx.x] = sh[1023];
}

__global__ void scan_partials(int* bsum, int nb) {
    __shared__ int sh[128];
    int tid = threadIdx.x;
    int v = (tid < nb) ? bsum[tid] : 0;
    sh[tid] = v;
    __syncthreads();
#pragma unroll
    for (int off = 1; off < 128; off <<= 1) {
        int t = (tid >= off) ? sh[tid - off] : 0;
        __syncthreads();
        sh[tid] += t;
        __syncthreads();
    }
    if (tid < nb) bsum[tid] = sh[tid] - v;
}

__global__ void scan_finish(const int* __restrict__ excl, const int* __restrict__ bsum,
                            int* __restrict__ rowptr, int* __restrict__ cursor, int n, int E) {
    int i = blockIdx.x * blockDim.x + threadIdx.x;
    if (i < n) {
        int v = excl[i] + bsum[i >> 10];
        rowptr[i] = v;
        cursor[i] = v;
    } else if (i == n) {
        rowptr[n] = E;
    }
}

__global__ void fill_csr(const int* __restrict__ src, const int* __restrict__ dst,
                         int* __restrict__ cursor, int* __restrict__ col, int E, int N) {
    int e = blockIdx.x * blockDim.x + threadIdx.x;
    if (e >= E) return;
    int d = dst[e];
    if ((unsigned)d >= (unsigned)N) return;
    int p = atomicAdd(&cursor[d], 1);
    col[p] = src[e];
}

// ---------------- MMA / LDSM / cp.async macros ----------------
#define LDSM_X4(r0, r1, r2, r3, addr) \
    asm volatile("ldmatrix.sync.aligned.m8n8.x4.shared.b16 {%0,%1,%2,%3}, [%4];" \
                 : "=r"(r0), "=r"(r1), "=r"(r2), "=r"(r3) : "r"(addr))
#define LDSM_X4_T(r0, r1, r2, r3, addr) \
    asm volatile("ldmatrix.sync.aligned.m8n8.x4.trans.shared.b16 {%0,%1,%2,%3}, [%4];" \
                 : "=r"(r0), "=r"(r1), "=r"(r2), "=r"(r3) : "r"(addr))
#define MMA_16816(d, a, b) \
    asm volatile("mma.sync.aligned.m16n8k16.row.col.f32.f16.f16.f32 " \
                 "{%0,%1,%2,%3}, {%4,%5,%6,%7}, {%8,%9}, {%0,%1,%2,%3};" \
                 : "+f"(d[0]), "+f"(d[1]), "+f"(d[2]), "+f"(d[3]) \
                 : "r"(a[0]), "r"(a[1]), "r"(a[2]), "r"(a[3]), "r"(b[0]), "r"(b[1]))
#define CP_ASYNC16(dst, src) \
    asm volatile("cp.async.cg.shared.global [%0], [%1], 16;" :: "r"(dst), "l"(src))
#define CP_ASYNC16_Z(dst, src) \
    asm volatile("cp.async.cg.shared.global [%0], [%1], 16, 0;" :: "r"(dst), "l"(src))
#define CP_COMMIT() asm volatile("cp.async.commit_group;")
#define CP_WAIT(n)  asm volatile("cp.async.wait_group %0;" :: "n"(n))

template <int FO>
__device__ __forceinline__ void stage_w(const float* __restrict__ W, char* Ws, int tid) {
    constexpr int WROWB = FO * 2;
    for (int i = tid; i < 128 * FO / 4; i += 256) {
        int k = i / (FO / 4);
        int c4 = i % (FO / 4);
        float4 v = ((const float4*)W)[(size_t)k * (FO / 4) + c4];
        __half2 h0 = __floats2half2_rn(v.x, v.y);
        __half2 h1 = __floats2half2_rn(v.z, v.w);
        uint2 u;
        u.x = *(unsigned*)&h0;
        u.y = *(unsigned*)&h1;
        int chunk = c4 >> 1;
        *(uint2*)&Ws[k * WROWB + (((chunk ^ (k & 7)) << 4) | ((c4 & 1) << 3))] = u;
    }
}

template <int FO, bool SCALE>
__device__ __forceinline__ void tile_compute(unsigned xs_base, unsigned ws_base,
                                             const float* __restrict__ dinv,
                                             __half* __restrict__ Yh, int row0, int N,
                                             int warp_m, int warp_n, int l) {
    constexpr int WN = FO / 2;
    constexpr int NFRAG = WN / 8;
    constexpr int XROWB = 256;
    constexpr int WROWB = FO * 2;

    float acc[2][NFRAG][4];
#pragma unroll
    for (int mf = 0; mf < 2; mf++)
#pragma unroll
        for (int nf = 0; nf < NFRAG; nf++)
#pragma unroll
            for (int c = 0; c < 4; c++) acc[mf][nf][c] = 0.f;

#pragma unroll
    for (int ks = 0; ks < 8; ks++) {
        unsigned a[2][4];
#pragma unroll
        for (int mf = 0; mf < 2; mf++) {
            int row = warp_m * 32 + mf * 16 + (l & 15);
            int colh = ks * 16 + (l >> 4) * 8;
            unsigned addr = xs_base + row * XROWB + ((((colh >> 3) ^ (row & 7))) << 4);
            LDSM_X4(a[mf][0], a[mf][1], a[mf][2], a[mf][3], addr);
        }
        unsigned b[NFRAG][2];
#pragma unroll
        for (int g2 = 0; g2 < NFRAG / 2; g2++) {
            int brow = ks * 16 + (l & 15);
            int bcol = warp_n * WN + g2 * 16 + (l >> 4) * 8;
            unsigned addr = ws_base + brow * WROWB + ((((bcol >> 3) ^ (brow & 7))) << 4);
            unsigned r0, r1, r2, r3;
            LDSM_X4_T(r0, r1, r2, r3, addr);
            b[2 * g2][0] = r0; b[2 * g2][1] = r1;
            b[2 * g2 + 1][0] = r2; b[2 * g2 + 1][1] = r3;
        }
#pragma unroll
        for (int mf = 0; mf < 2; mf++)
#pragma unroll
            for (int nf = 0; nf < NFRAG; nf++)
                MMA_16816(acc[mf][nf], a[mf], b[nf]);
    }

    int g = l >> 2;
    int c2 = (l & 3) * 2;
#pragma unroll
    for (int mf = 0; mf < 2; mf++) {
        int r_lo = row0 + warp_m * 32 + mf * 16 + g;
        int r_hi = r_lo + 8;
        float di_lo = 1.f, di_hi = 1.f;
        if (SCALE) {
            di_lo = (r_lo < N) ? dinv[r_lo] : 0.f;
            di_hi = (r_hi < N) ? dinv[r_hi] : 0.f;
        }
#pragma unroll
        for (int nf = 0; nf < NFRAG; nf++) {
            int col = warp_n * WN + nf * 8 + c2;
            if (r_lo < N) {
                __half2 h = SCALE ? __floats2half2_rn(di_lo * acc[mf][nf][0], di_lo * acc[mf][nf][1])
                                  : __floats2half2_rn(acc[mf][nf][0], acc[mf][nf][1]);
                *(__half2*)&Yh[(size_t)r_lo * FO + col] = h;
            }
            if (r_hi < N) {
                __half2 h = SCALE ? __floats2half2_rn(di_hi * acc[mf][nf][2], di_hi * acc[mf][nf][3])
                                  : __floats2half2_rn(acc[mf][nf][2], acc[mf][nf][3]);
                *(__half2*)&Yh[(size_t)r_hi * FO + col] = h;
            }
        }
    }
}

// ---------------- gemm1: fp32 input, UNSCALED output ----------------
__launch_bounds__(256, 2)
__global__ void gemm_hmma_f32(const float* __restrict__ Xin, const float* __restrict__ W,
                              __half* __restrict__ Yh, int N) {
    constexpr int FO = 128;
    constexpr int BM = 128;
    constexpr int XROWB = 256;

    extern __shared__ char sm[];
    char* Xs = sm;
    char* Ws = sm + BM * XROWB;

    int tid = threadIdx.x;
    int warp = tid >> 5;
    int l = tid & 31;
    int warp_m = warp & 3;
    int warp_n = warp >> 2;

    stage_w<FO>(W, Ws, tid);

    unsigned xs_base = (unsigned)__cvta_generic_to_shared(Xs);
    unsigned ws_base = (unsigned)__cvta_generic_to_shared(Ws);

    int tiles = (N + BM - 1) / BM;
    int t = blockIdx.x;
    uint4 pf[8];

    auto ldg_tile = [&](int row0) {
#pragma unroll
        for (int j = 0; j < 8; j++) {
            int i = tid + j * 256;
            int r = i >> 4;
            int q = i & 15;
            int gr = row0 + r;
            uint4 v = make_uint4(0, 0, 0, 0);
            if (gr < N) {
                const float4* p = (const float4*)Xin + (size_t)gr * 32 + q * 2;
                float4 f0 = p[0];
                float4 f1 = p[1];
                __half2 h0 = __floats2half2_rn(f0.x, f0.y);
                __half2 h1 = __floats2half2_rn(f0.z, f0.w);
                __half2 h2 = __floats2half2_rn(f1.x, f1.y);
                __half2 h3 = __floats2half2_rn(f1.z, f1.w);
                v.x = *(unsigned*)&h0;
                v.y = *(unsigned*)&h1;
                v.z = *(unsigned*)&h2;
                v.w = *(unsigned*)&h3;
            }
            pf[j] = v;
        }
    };

    if (t < tiles) ldg_tile(t * BM);

    for (; t < tiles; t += gridDim.x) {
        int row0 = t * BM;
#pragma unroll
        for (int j = 0; j < 8; j++) {
            int i = tid + j * 256;
            int r = i >> 4;
            int q = i & 15;
            *(uint4*)&Xs[r * XROWB + ((q ^ (r & 7)) << 4)] = pf[j];
        }
        __syncthreads();
        int tn = t + gridDim.x;
        if (tn < tiles) ldg_tile(tn * BM);
        tile_compute<FO, false>(xs_base, ws_base, nullptr, Yh, row0, N, warp_m, warp_n, l);
        __syncthreads();
    }
}

// ---------------- gemm fp16 input: cp.async double-buffered, SCALED output ----------------
template <int FO>
__launch_bounds__(256, 2)
__global__ void gemm_hmma_ca(const __half* __restrict__ Xin, const float* __restrict__ W,
                             const float* __restrict__ dinv, __half* __restrict__ Yh, int N) {
    constexpr int BM = 128;
    constexpr int XROWB = 256;
    constexpr int XBUF = BM * XROWB;

    extern __shared__ char sm[];
    char* Xs = sm;
    char* Ws = sm + 2 * XBUF;

    int tid = threadIdx.x;
    int warp = tid >> 5;
    int l = tid & 31;
    int warp_m = warp & 3;
    int warp_n = warp >> 2;

    stage_w<FO>(W, Ws, tid);

    unsigned xs_base0 = (unsigned)__cvta_generic_to_shared(Xs);
    unsigned ws_base = (unsigned)__cvta_generic_to_shared(Ws);

    int tiles = (N + BM - 1) / BM;
    int t = blockIdx.x;

    auto stage_x = [&](int tile, int buf) {
        int row0 = tile * BM;
        unsigned base = xs_base0 + buf * XBUF;
#pragma unroll
        for (int j = 0; j < 8; j++) {
            int i = tid + j * 256;
            int r = i >> 4;
            int q = i & 15;
            int gr = row0 + r;
            unsigned dst = base + r * XROWB + ((q ^ (r & 7)) << 4);
            const __half* src = Xin + (size_t)(gr < N ? gr : 0) * 128 + q * 8;
            if (gr < N) CP_ASYNC16(dst, src);
            else        CP_ASYNC16_Z(dst, src);
        }
        CP_COMMIT();
    };

    int buf = 0;
    if (t < tiles) stage_x(t, 0);

    for (; t < tiles; t += gridDim.x) {
        int tn = t + gridDim.x;
        if (tn < tiles) {
            stage_x(tn, buf ^ 1);
            CP_WAIT(1);
        } else {
            CP_WAIT(0);
        }
        __syncthreads();
        tile_compute<FO, true>(xs_base0 + buf * XBUF, ws_base, dinv, Yh, t * BM, N,
                               warp_m, warp_n, l);
        __syncthreads();
        buf ^= 1;
    }
}

// ---------------- aggregation helpers ----------------
__device__ __forceinline__ void unpack_add8(uint4 u, float* acc) {
    float2 f;
    f = __half22float2(*(__half2*)&u.x); acc[0] += f.x; acc[1] += f.y;
    f = __half22float2(*(__half2*)&u.y); acc[2] += f.x; acc[3] += f.y;
    f = __half22float2(*(__half2*)&u.z); acc[4] += f.x; acc[5] += f.y;
    f = __half22float2(*(__half2*)&u.w); acc[6] += f.x; acc[7] += f.y;
}
__device__ __forceinline__ void unpack_fma8(uint4 u, float s, float* acc) {
    float2 f;
    f = __half22float2(*(__half2*)&u.x); acc[0] = fmaf(s, f.x, acc[0]); acc[1] = fmaf(s, f.y, acc[1]);
    f = __half22float2(*(__half2*)&u.y); acc[2] = fmaf(s, f.x, acc[2]); acc[3] = fmaf(s, f.y, acc[3]);
    f = __half22float2(*(__half2*)&u.z); acc[4] = fmaf(s, f.x, acc[4]); acc[5] = fmaf(s, f.y, acc[5]);
    f = __half22float2(*(__half2*)&u.w); acc[6] = fmaf(s, f.x, acc[6]); acc[7] = fmaf(s, f.y, acc[7]);
}
__device__ __forceinline__ void unpack_add4(uint2 u, float* acc) {
    float2 f;
    f = __half22float2(*(__half2*)&u.x); acc[0] += f.x; acc[1] += f.y;
    f = __half22float2(*(__half2*)&u.y); acc[2] += f.x; acc[3] += f.y;
}

// layer-1 agg: Y UNSCALED -> dinv[s] per edge; 4 edges in flight per half-warp
__global__ void agg_relu128_l1(const int* __restrict__ rowptr, const int* __restrict__ col,
                               const __half* __restrict__ Yh, const float* __restrict__ dinv,
                               const float* __restrict__ bias, __half* __restrict__ H, int N) {
    int node = (blockIdx.x * blockDim.x + threadIdx.x) >> 5;
    int lane = threadIdx.x & 31;
    if (node >= N) return;
    int hf = lane >> 4;
    int l16 = lane & 15;
    const uint4* Y4 = (const uint4*)Yh;

    float di = dinv[node];
    float acc[8];
#pragma unroll
    for (int k = 0; k < 8; k++) acc[k] = 0.f;
    if (hf == 0)
        unpack_fma8(Y4[(size_t)node * 16 + l16], di, acc);

    int end = rowptr[node + 1];
    int j = rowptr[node] + hf;
    for (; j + 6 < end; j += 8) {
        int s0 = __ldg(&col[j]);
        int s1 = __ldg(&col[j + 2]);
        int s2 = __ldg(&col[j + 4]);
        int s3 = __ldg(&col[j + 6]);
        float d0 = __ldg(&dinv[s0]);
        float d1 = __ldg(&dinv[s1]);
        float d2 = __ldg(&dinv[s2]);
        float d3 = __ldg(&dinv[s3]);
        uint4 a = Y4[(size_t)s0 * 16 + l16];
        uint4 b = Y4[(size_t)s1 * 16 + l16];
        uint4 c = Y4[(size_t)s2 * 16 + l16];
        uint4 d = Y4[(size_t)s3 * 16 + l16];
        unpack_fma8(a, d0, acc);
        unpack_fma8(b, d1, acc);
        unpack_fma8(c, d2, acc);
        unpack_fma8(d, d3, acc);
    }
    for (; j + 2 < end; j += 4) {
        int s0 = __ldg(&col[j]);
        int s1 = __ldg(&col[j + 2]);
        float d0 = __ldg(&dinv[s0]);
        float d1 = __ldg(&dinv[s1]);
        uint4 a = Y4[(size_t)s0 * 16 + l16];
        uint4 b = Y4[(size_t)s1 * 16 + l16];
        unpack_fma8(a, d0, acc);
        unpack_fma8(b, d1, acc);
    }
    for (; j < end; j += 2) {
        int s = __ldg(&col[j]);
        float ds = __ldg(&dinv[s]);
        unpack_fma8(Y4[(size_t)s * 16 + l16], ds, acc);
    }
#pragma unroll
    for (int k = 0; k < 8; k++)
        acc[k] += __shfl_xor_sync(0xFFFFFFFFu, acc[k], 16);

    if (hf == 0) {
        float4 b0 = ((const float4*)bias)[l16 * 2];
        float4 b1 = ((const float4*)bias)[l16 * 2 + 1];
        __half2 p0 = __floats2half2_rn(fmaxf(fmaf(di, acc[0], b0.x), 0.f),
                                       fmaxf(fmaf(di, acc[1], b0.y), 0.f));
        __half2 p1 = __floats2half2_rn(fmaxf(fmaf(di, acc[2], b0.z), 0.f),
                                       fmaxf(fmaf(di, acc[3], b0.w), 0.f));
        __half2 p2 = __floats2half2_rn(fmaxf(fmaf(di, acc[4], b1.x), 0.f),
                                       fmaxf(fmaf(di, acc[5], b1.y), 0.f));
        __half2 p3 = __floats2half2_rn(fmaxf(fmaf(di, acc[6], b1.z), 0.f),
                                       fmaxf(fmaf(di, acc[7], b1.w), 0.f));
        uint4 u;
        u.x = *(unsigned*)&p0;
        u.y = *(unsigned*)&p1;
        u.z = *(unsigned*)&p2;
        u.w = *(unsigned*)&p3;
        ((uint4*)H)[(size_t)node * 16 + l16] = u;
    }
}

// layer 2: Y pre-scaled; 4 edges in flight per half-warp
__global__ void agg_relu128(const int* __restrict__ rowptr, const int* __restrict__ col,
                            const __half* __restrict__ Yh, const float* __restrict__ dinv,
                            const float* __restrict__ bias, __half* __restrict__ H, int N) {
    int node = (blockIdx.x * blockDim.x + threadIdx.x) >> 5;
    int lane = threadIdx.x & 31;
    if (node >= N) return;
    int hf = lane >> 4;
    int l16 = lane & 15;
    const uint4* Y4 = (const uint4*)Yh;

    float acc[8];
#pragma unroll
    for (int k = 0; k < 8; k++) acc[k] = 0.f;
    if (hf == 0)
        unpack_add8(Y4[(size_t)node * 16 + l16], acc);

    int end = rowptr[node + 1];
    int j = rowptr[node] + hf;
    for (; j + 6 < end; j += 8) {
        int s0 = __ldg(&col[j]);
        int s1 = __ldg(&col[j + 2]);
        int s2 = __ldg(&col[j + 4]);
        int s3 = __ldg(&col[j + 6]);
        uint4 a = Y4[(size_t)s0 * 16 + l16];
        uint4 b = Y4[(size_t)s1 * 16 + l16];
        uint4 c = Y4[(size_t)s2 * 16 + l16];
        uint4 d = Y4[(size_t)s3 * 16 + l16];
        unpack_add8(a, acc);
        unpack_add8(b, acc);
        unpack_add8(c, acc);
        unpack_add8(d, acc);
    }
    for (; j + 2 < end; j += 4) {
        int s0 = __ldg(&col[j]);
        int s1 = __ldg(&col[j + 2]);
        uint4 a = Y4[(size_t)s0 * 16 + l16];
        uint4 b = Y4[(size_t)s1 * 16 + l16];
        unpack_add8(a, acc);
        unpack_add8(b, acc);
    }
    for (; j < end; j += 2) {
        int s = __ldg(&col[j]);
        unpack_add8(Y4[(size_t)s * 16 + l16], acc);
    }
#pragma unroll
    for (int k = 0; k < 8; k++)
        acc[k] += __shfl_xor_sync(0xFFFFFFFFu, acc[k], 16);

    if (hf == 0) {
        float di = dinv[node];
        float4 b0 = ((const float4*)bias)[l16 * 2];
        float4 b1 = ((const float4*)bias)[l16 * 2 + 1];
        __half2 p0 = __floats2half2_rn(fmaxf(fmaf(di, acc[0], b0.x), 0.f),
                                       fmaxf(fmaf(di, acc[1], b0.y), 0.f));
        __half2 p1 = __floats2half2_rn(fmaxf(fmaf(di, acc[2], b0.z), 0.f),
                                       fmaxf(fmaf(di, acc[3], b0.w), 0.f));
        __half2 p2 = __floats2half2_rn(fmaxf(fmaf(di, acc[4], b1.x), 0.f),
                                       fmaxf(fmaf(di, acc[5], b1.y), 0.f));
        __half2 p3 = __floats2half2_rn(fmaxf(fmaf(di, acc[6], b1.z), 0.f),
                                       fmaxf(fmaf(di, acc[7], b1.w), 0.f));
        uint4 u;
        u.x = *(unsigned*)&p0;
        u.y = *(unsigned*)&p1;
        u.z = *(unsigned*)&p2;
        u.w = *(unsigned*)&p3;
        ((uint4*)H)[(size_t)node * 16 + l16] = u;
    }
}

// layer 3: half-warp edges, 4 in flight, + log_softmax over 64 ch
__global__ void agg_lsm64(const int* __restrict__ rowptr, const int* __restrict__ col,
                          const __half* __restrict__ Yh, const float* __restrict__ dinv,
                          const float* __restrict__ bias, float4* __restrict__ Out, int N) {
    int node = (blockIdx.x * blockDim.x + threadIdx.x) >> 5;
    int lane = threadIdx.x & 31;
    if (node >= N) return;
    int hf = lane >> 4;
    int l16 = lane & 15;
    const uint2* Y2 = (const uint2*)Yh;

    float acc[4];
#pragma unroll
    for (int k = 0; k < 4; k++) acc[k] = 0.f;
    if (hf == 0)
        unpack_add4(Y2[(size_t)node * 16 + l16], acc);

    int end = rowptr[node + 1];
    int j = rowptr[node] + hf;
    for (; j + 6 < end; j += 8) {
        int s0 = __ldg(&col[j]);
        int s1 = __ldg(&col[j + 2]);
        int s2 = __ldg(&col[j + 4]);
        int s3 = __ldg(&col[j + 6]);
        uint2 a = Y2[(size_t)s0 * 16 + l16];
        uint2 b = Y2[(size_t)s1 * 16 + l16];
        uint2 c = Y2[(size_t)s2 * 16 + l16];
        uint2 d = Y2[(size_t)s3 * 16 + l16];
        unpack_add4(a, acc);
        unpack_add4(b, acc);
        unpack_add4(c, acc);
        unpack_add4(d, acc);
    }
    for (; j + 2 < end; j += 4) {
        int s0 = __ldg(&col[j]);
        int s1 = __ldg(&col[j + 2]);
        uint2 a = Y2[(size_t)s0 * 16 + l16];
        uint2 b = Y2[(size_t)s1 * 16 + l16];
        unpack_add4(a, acc);
        unpack_add4(b, acc);
    }
    for (; j < end; j += 2) {
        int s = __ldg(&col[j]);
        unpack_add4(Y2[(size_t)s * 16 + l16], acc);
    }
#pragma unroll
    for (int k = 0; k < 4; k++)
        acc[k] += __shfl_xor_sync(0xFFFFFFFFu, acc[k], 16);

    float di = dinv[node];
    float4 b = ((const float4*)bias)[l16];
    float v0 = fmaf(di, acc[0], b.x);
    float v1 = fmaf(di, acc[1], b.y);
    float v2 = fmaf(di, acc[2], b.z);
    float v3 = fmaf(di, acc[3], b.w);
    float m = fmaxf(fmaxf(v0, v1), fmaxf(v2, v3));
#pragma unroll
    for (int o = 8; o > 0; o >>= 1)
        m = fmaxf(m, __shfl_xor_sync(0xFFFFFFFFu, m, o));
    float s = expf(v0 - m) + expf(v1 - m) + expf(v2 - m) + expf(v3 - m);
#pragma unroll
    for (int o = 8; o > 0; o >>= 1)
        s += __shfl_xor_sync(0xFFFFFFFFu, s, o);
    float ls = m + logf(s);
    if (hf == 0)
        Out[(size_t)node * 16 + l16] = make_float4(v0 - ls, v1 - ls, v2 - ls, v3 - ls);
}

// ---------------- driver ----------------
extern "C" void kernel_launch(void* const* d_in, const int* in_sizes, int n_in,
                              void* d_out, int out_size) {
    const float* x   = (const float*)d_in[0];
    const int*   ei  = (const int*)d_in[1];
    const float* W1  = (const float*)d_in[2];
    const float* b1  = (const float*)d_in[3];
    const float* W2  = (const float*)d_in[4];
    const float* b2  = (const float*)d_in[5];
    const float* W3  = (const float*)d_in[6];
    const float* b3  = (const float*)d_in[7];
    float* out = (float*)d_out;

    int N = in_sizes[0] / 128;
    int E = in_sizes[1] / 2;
    const int* src = ei;
    const int* dst = ei + E;

    __half *yh, *h;
    float* dinv;
    int *cnt, *excl, *bsum, *rowptr, *cursor, *col;
    cudaGetSymbolAddress((void**)&yh, g_yh);
    cudaGetSymbolAddress((void**)&h, g_h);
    cudaGetSymbolAddress((void**)&dinv, g_dinv);
    cudaGetSymbolAddress((void**)&cnt, g_cnt);
    cudaGetSymbolAddress((void**)&excl, g_excl);
    cudaGetSymbolAddress((void**)&bsum, g_bsum);
    cudaGetSymbolAddress((void**)&rowptr, g_rowptr);
    cudaGetSymbolAddress((void**)&cursor, g_cursor);
    cudaGetSymbolAddress((void**)&col, g_col);

    static cudaStream_t s_side = 0;
    static cudaEvent_t ev_fork = 0, ev_join = 0;
    static bool inited = false;
    if (!inited) {
        inited = true;
        if (cudaStreamCreateWithFlags(&s_side, cudaStreamNonBlocking) != cudaSuccess)
            s_side = 0;
        if (s_side) {
            if (cudaEventCreateWithFlags(&ev_fork, cudaEventDisableTiming) != cudaSuccess ||
                cudaEventCreateWithFlags(&ev_join, cudaEventDisableTiming) != cudaSuccess)
                s_side = 0;
        }
    }
    bool fork = (s_side != 0);
    cudaStream_t sc = fork ? s_side : 0;

    constexpr int SMEM_G1    = 128 * 256 + 128 * 256;    // 64 KB
    constexpr int SMEM_CA128 = 2 * 32768 + 128 * 256;    // 96 KB
    constexpr int SMEM_CA64  = 2 * 32768 + 128 * 128;    // 80 KB
    cudaFuncSetAttribute(gemm_hmma_f32,     cudaFuncAttributeMaxDynamicSharedMemorySize, SMEM_G1);
    cudaFuncSetAttribute(gemm_hmma_ca<128>, cudaFuncAttributeMaxDynamicSharedMemorySize, SMEM_CA128);
    cudaFuncSetAttribute(gemm_hmma_ca<64>,  cudaFuncAttributeMaxDynamicSharedMemorySize, SMEM_CA64);

    int nb_nodes = (N + 255) / 256;
    int nb_edges = (E + 255) / 256;
    int nb_scan  = (N + 1023) / 1024;
    int tiles = (N + 127) / 128;
    int gemm_blocks = tiles < 296 ? tiles : 296;
    int agg_blocks  = (int)(((size_t)N * 32 + 255) / 256);

    // ---- fork FROM the capture-origin stream, then prep || gemm1 ----
    if (fork) {
        cudaEventRecord(ev_fork, 0);
        cudaStreamWaitEvent(s_side, ev_fork, 0);
    }
    zero_cnt<<<nb_nodes, 256, 0, sc>>>(cnt, N);
    count_deg<<<nb_edges, 256, 0, sc>>>(dst, cnt, E, N);
    scan_block_dinv<<<nb_scan, 1024, 0, sc>>>(cnt, excl, bsum, dinv, N);
    gemm_hmma_f32<<<gemm_blocks, 256, SMEM_G1>>>(x, W1, yh, N);   // default stream
    scan_partials<<<1, 128, 0, sc>>>(bsum, nb_scan);
    scan_finish<<<(N + 256) / 256, 256, 0, sc>>>(excl, bsum, rowptr, cursor, N, E);
    fill_csr<<<nb_edges, 256, 0, sc>>>(src, dst, cursor, col, E, N);
    if (fork) {
        cudaEventRecord(ev_join, s_side);
        cudaStreamWaitEvent(0, ev_join, 0);
    }

    // ---- layer 1 aggregation (applies dinv[s] per edge) ----
    agg_relu128_l1<<<agg_blocks, 256>>>(rowptr, col, yh, dinv, b1, h, N);
    // ---- layer 2 ----
    gemm_hmma_ca<128><<<gemm_blocks, 256, SMEM_CA128>>>(h, W2, dinv, yh, N);
    agg_relu128<<<agg_blocks, 256>>>(rowptr, col, yh, dinv, b2, h, N);
    // ---- layer 3 ----
    gemm_hmma_ca<64><<<gemm_blocks, 256, SMEM_CA64>>>(h, W3, dinv, yh, N);
    agg_lsm64<<<agg_blocks, 256>>>(rowptr, col, yh, dinv, b3, (float4*)out, N);
}